// round 7
// baseline (speedup 1.0000x reference)
#include <cuda_runtime.h>

#define B_   4096
#define T_   64
#define OBS_ 64
#define H_   64
#define A_   8
#define S_   201
#define G_   16
#define NTHR 256
#define STD  36    // duplicated-layout stride (floats): 16 elems * 2 + 4 pad
#define STP  20    // Pt stride (floats)

typedef unsigned long long u64;
typedef unsigned int u32;

__device__ __forceinline__ u64 fma2(u64 a, u64 b, u64 c) {
    u64 d;
    asm("fma.rn.f32x2 %0, %1, %2, %3;" : "=l"(d) : "l"(a), "l"(b), "l"(c));
    return d;
}
__device__ __forceinline__ float2 unpack2(u64 a) {
    u32 lo, hi;
    asm("mov.b64 {%0, %1}, %2;" : "=r"(lo), "=r"(hi) : "l"(a));
    float2 r; r.x = __uint_as_float(lo); r.y = __uint_as_float(hi);
    return r;
}

// XLA/Eigen f32 fast-tanh clone — decision-critical, validated R3/R5. DO NOT TOUCH.
__device__ __forceinline__ float tanh_xla(float x) {
    float xc = fminf(fmaxf(x, -7.90531110763549805f), 7.90531110763549805f);
    float x2 = xc * xc;
    float p = -2.76076847742355e-16f;
    p = __fmaf_rn(p, x2, 2.00018790482477e-13f);
    p = __fmaf_rn(p, x2, -8.60467152213735e-11f);
    p = __fmaf_rn(p, x2, 5.12229709037114e-08f);
    p = __fmaf_rn(p, x2, 1.48572235717979e-05f);
    p = __fmaf_rn(p, x2, 6.37261928875436e-04f);
    p = __fmaf_rn(p, x2, 4.89352455891786e-03f);
    float num = xc * p;
    float q = 1.19825839466702e-06f;
    q = __fmaf_rn(q, x2, 1.18534705686654e-04f);
    q = __fmaf_rn(q, x2, 2.26843463243900e-03f);
    q = __fmaf_rn(q, x2, 4.89352518554385e-03f);
    float r = __fdiv_rn(num, q);
    return (fabsf(x) < 0.0004f) ? x : r;
}

#define OFF_VAL ((size_t)B_ * T_ * A_)
#define OFF_STK (OFF_VAL + (size_t)T_ * B_)
#define OFF_PTR (OFF_STK + (size_t)B_ * S_ * H_)

// shared memory layout (float offsets)
#define SM_W1T   0                         // [128][64]
#define SM_W2T   (SM_W1T + 8192)           // [64][64]
#define SM_WST   (SM_W2T + 4096)           // [64][3]
#define SM_WHT   (SM_WST + 192)            // [64][9]  (Wp rows 0..7, Wv row 8)
#define SM_B1    (SM_WHT + 576)            // 64
#define SM_B2    (SM_B1 + 64)              // 64
#define SM_BSS   (SM_B2 + 64)              // 4  (3 used)
#define SM_BHS   (SM_BSS + 4)              // 12 (9 used)
#define SM_IN    (SM_BHS + 12)             // [128][STD] duplicated
#define SM_HT    (SM_IN + 128 * STD)       // [64][STD]  duplicated
#define SM_PT    (SM_HT + 64 * STD)        // [64][STP]
#define SM_LS    (SM_PT + 64 * STP)        // [16][4]
#define SM_INTS  (SM_LS + 64)              // ptrS(16) + wbits(112)
#define SMEM_FLOATS (SM_INTS + 128)
#define SMEM_BYTES  (SMEM_FLOATS * 4)

__global__ void __launch_bounds__(NTHR, 2) stacknet_scan(
    const float* __restrict__ x,   const float* __restrict__ stack_in,
    const int*   __restrict__ ptr_in,
    const float* __restrict__ W1,  const float* __restrict__ b1,
    const float* __restrict__ W2,  const float* __restrict__ b2,
    const float* __restrict__ Ws,  const float* __restrict__ bsv,
    const float* __restrict__ Wp,  const float* __restrict__ bp,
    const float* __restrict__ Wv,  const float* __restrict__ bv,
    float* __restrict__ out)
{
    extern __shared__ float sm[];
    float* W1t = sm + SM_W1T;
    float* W2t = sm + SM_W2T;
    float* Wst = sm + SM_WST;
    float* Wht = sm + SM_WHT;
    float* b1s = sm + SM_B1;
    float* b2s = sm + SM_B2;
    float* bss = sm + SM_BSS;
    float* bhs = sm + SM_BHS;
    float* InT = sm + SM_IN;      // duplicated: value v of elem e at [f*STD + 2e] as {v,v}
    float* Ht  = sm + SM_HT;      // duplicated likewise
    float* Pt  = sm + SM_PT;      // [feature j][elem r]
    float* Ls  = sm + SM_LS;
    int*   ptrS  = (int*)(sm + SM_INTS);
    u32*   wbits = (u32*)(ptrS + 16);

    const int tid  = threadIdx.x;
    const int base = blockIdx.x * G_;

    // ---- weight prologue ----
    for (int i = tid; i < 8192; i += NTHR) { int j = i >> 7, k = i & 127; W1t[k * 64 + j] = W1[i]; }
    for (int i = tid; i < 4096; i += NTHR) { int j = i >> 6, k = i & 63;  W2t[k * 64 + j] = W2[i]; }
    for (int i = tid; i < 192;  i += NTHR) { int h = i >> 6, k = i & 63;  Wst[k * 3 + h] = Ws[i]; }
    for (int i = tid; i < 512;  i += NTHR) { int h = i >> 6, k = i & 63;  Wht[k * 9 + h] = Wp[i]; }
    for (int i = tid; i < 64;   i += NTHR) { Wht[i * 9 + 8] = Wv[i]; }
    if (tid < 64) { b1s[tid] = b1[tid]; b2s[tid] = b2[tid]; }
    if (tid < 3)              bss[tid] = bsv[tid];
    if (tid >= 3 && tid < 11) bhs[tid - 3] = bp[tid - 3];
    if (tid == 11)            bhs[8] = bv[0];
    for (int i = tid; i < G_ * 7; i += NTHR) wbits[i] = 0;
    if (tid < G_) ptrS[tid] = ptr_in[base + tid];
    __syncthreads();

    // compute map: rows r0=2*q2, r0+1 ; cols j0=2*c, j0+1
    const int q2 = tid & 7, c = tid >> 3;
    // IO map (tid < 128): element e, feature segment seg
    const int e = tid & 15, seg = (tid >> 4) & 7;
    const bool io = tid < 128;

    const size_t xrow = (size_t)(base + e) * T_ * OBS_;
    const size_t srow = (size_t)(base + e) * S_;
    float* ostk = out + OFF_STK;

    // register arrays (NOT float4 pairs — R6's cross-variable pointer-pun was UB)
    __align__(16) float xs[8], cs[8], pm[8], pp[8];
    if (io) {
        int p0 = ptrS[e];
        const float4* xv = (const float4*)(x + xrow + seg * 8);
        *(float4*)&xs[0] = xv[0]; *(float4*)&xs[4] = xv[1];
        const float4* sv = (const float4*)(stack_in + (srow + p0) * H_ + seg * 8);
        *(float4*)&cs[0] = sv[0]; *(float4*)&cs[4] = sv[1];
        #pragma unroll
        for (int i = 0; i < 8; ++i) {
            int f = seg * 8 + i;
            *(float2*)&InT[f * STD + 2 * e]        = make_float2(xs[i], xs[i]);
            *(float2*)&InT[(64 + f) * STD + 2 * e] = make_float2(cs[i], cs[i]);
        }
    }

    for (int t = 0; t < T_; ++t) {
        __syncthreads();   // A: InT ready; orders prev push STG + wbits

        const int p = ptrS[e];
        if (io && t + 1 < T_) {
            // vectorized prefetch of x_{t+1} and both candidate next-top rows
            const int rm = p > 0 ? p - 1 : 0;
            const int rp = p + 1;
            const float* bm = ((wbits[e * 7 + (rm >> 5)] >> (rm & 31)) & 1u) ? ostk : stack_in;
            const float* bq = ((wbits[e * 7 + (rp >> 5)] >> (rp & 31)) & 1u) ? ostk : stack_in;
            const float4* xv = (const float4*)(x + xrow + (size_t)(t + 1) * OBS_ + seg * 8);
            *(float4*)&xs[0] = xv[0]; *(float4*)&xs[4] = xv[1];
            const float4* mv = (const float4*)(bm + (srow + rm) * H_ + seg * 8);
            *(float4*)&pm[0] = mv[0]; *(float4*)&pm[4] = mv[1];
            const float4* qv = (const float4*)(bq + (srow + rp) * H_ + seg * 8);
            *(float4*)&pp[0] = qv[0]; *(float4*)&pp[4] = qv[1];
        }

        // ---- W1: [16x128]@[128x64], 2x2 tile, dup'd input, 4 instr / 4 MACs ----
        u64 a0 = 0ull, a1 = 0ull;
        {
            const float* inb = &InT[4 * q2];
            const float* wb  = &W1t[2 * c];
            #pragma unroll 8
            for (int k = 0; k < 128; ++k) {
                ulonglong2 in = *(const ulonglong2*)(inb + k * STD);  // {r0,r0},{r1,r1}
                u64 w = *(const u64*)(wb + k * 64);                   // {wj0,wj1}
                a0 = fma2(in.x, w, a0);
                a1 = fma2(in.y, w, a1);
            }
        }
        {
            float2 v0 = unpack2(a0), v1 = unpack2(a1);
            int j0 = 2 * c, r0 = 2 * q2;
            float h00 = tanh_xla(v0.x + b1s[j0]);
            float h01 = tanh_xla(v0.y + b1s[j0 + 1]);
            float h10 = tanh_xla(v1.x + b1s[j0]);
            float h11 = tanh_xla(v1.y + b1s[j0 + 1]);
            *(float2*)&Ht[j0 * STD + 2 * r0]             = make_float2(h00, h00);
            *(float2*)&Ht[(j0 + 1) * STD + 2 * r0]       = make_float2(h01, h01);
            *(float2*)&Ht[j0 * STD + 2 * (r0 + 1)]       = make_float2(h10, h10);
            *(float2*)&Ht[(j0 + 1) * STD + 2 * (r0 + 1)] = make_float2(h11, h11);
        }
        __syncthreads();   // B

        // ---- W2: [16x64]@[64x64] ----
        a0 = 0ull; a1 = 0ull;
        {
            const float* inb = &Ht[4 * q2];
            const float* wb  = &W2t[2 * c];
            #pragma unroll 8
            for (int k = 0; k < 64; ++k) {
                ulonglong2 in = *(const ulonglong2*)(inb + k * STD);
                u64 w = *(const u64*)(wb + k * 64);
                a0 = fma2(in.x, w, a0);
                a1 = fma2(in.y, w, a1);
            }
        }
        {
            float2 v0 = unpack2(a0), v1 = unpack2(a1);
            int j0 = 2 * c, r0 = 2 * q2;
            Pt[j0 * STP + r0]           = tanh_xla(v0.x + b2s[j0]);
            Pt[(j0 + 1) * STP + r0]     = tanh_xla(v0.y + b2s[j0 + 1]);
            Pt[j0 * STP + r0 + 1]       = tanh_xla(v1.x + b2s[j0]);
            Pt[(j0 + 1) * STP + r0 + 1] = tanh_xla(v1.y + b2s[j0 + 1]);
        }
        __syncthreads();   // C: Pt ready

        // ---- heads, overlapped: stack-head (tid<48) || policy/value (tid>=112) ----
        if (tid < 48) {
            int ee = tid / 3, h = tid - 3 * ee;
            float acc = 0.0f;
            #pragma unroll 8
            for (int k = 0; k < 64; ++k) acc = __fmaf_rn(Pt[k * STP + ee], Wst[k * 3 + h], acc);
            Ls[ee * 4 + h] = acc + bss[h];
        } else if (tid >= 112) {
            int o = tid - 112, ee = o / 9, h = o - 9 * ee;
            float acc = 0.0f;
            #pragma unroll 8
            for (int k = 0; k < 64; ++k) acc = __fmaf_rn(Pt[k * STP + ee], Wht[k * 9 + h], acc);
            acc += bhs[h];
            if (h < 8) out[((size_t)(base + ee) * T_ + t) * A_ + h] = acc;
            else       out[OFF_VAL + (size_t)t * B_ + (base + ee)] = acc;
        }
        __syncthreads();   // D: Ls ready

        // ---- argmax + stack update (IO threads) ----
        if (io) {
            float l0 = Ls[e * 4], l1 = Ls[e * 4 + 1], l2 = Ls[e * 4 + 2];
            int op = 0; float bst = l0;
            if (l1 > bst) { bst = l1; op = 1; }
            if (l2 > bst) { op = 2; }
            if (tid < 16) {    // e == tid
                int np = p + op - 1; np = np < 0 ? 0 : np;
                ptrS[e] = np;
                if (op == 2) wbits[e * 7 + (p >> 5)] |= (1u << (p & 31));
            }
            if (op == 2) {
                // gather p column for element e, push write-through, next top = stack[p+1]
                float pv[8];
                #pragma unroll
                for (int i = 0; i < 8; ++i) pv[i] = Pt[(seg * 8 + i) * STP + e];
                float4* dst = (float4*)(ostk + (srow + p) * H_ + seg * 8);
                dst[0] = make_float4(pv[0], pv[1], pv[2], pv[3]);
                dst[1] = make_float4(pv[4], pv[5], pv[6], pv[7]);
                #pragma unroll
                for (int i = 0; i < 8; ++i) cs[i] = pp[i];
            } else if (op == 0) {
                #pragma unroll
                for (int i = 0; i < 8; ++i) cs[i] = pm[i];    // next top = stack[p-1]
            }                                                  // op==1: keep cs
            if (t + 1 < T_) {
                #pragma unroll
                for (int i = 0; i < 8; ++i) {
                    int f = seg * 8 + i;
                    *(float2*)&InT[f * STD + 2 * e]        = make_float2(xs[i], xs[i]);
                    *(float2*)&InT[(64 + f) * STD + 2 * e] = make_float2(cs[i], cs[i]);
                }
            }
        }
    }

    if (tid < G_) out[OFF_PTR + base + tid] = (float)ptrS[tid];
    __syncthreads();

    // epilogue: copy never-written stack rows from input
    for (int it = tid; it < G_ * S_; it += NTHR) {
        int ee = it / S_, rr = it - S_ * ee;
        if (!((wbits[ee * 7 + (rr >> 5)] >> (rr & 31)) & 1u)) {
            const float4* src = (const float4*)(stack_in + ((size_t)(base + ee) * S_ + rr) * H_);
            float4* dst = (float4*)(out + OFF_STK + ((size_t)(base + ee) * S_ + rr) * H_);
            #pragma unroll
            for (int v = 0; v < 16; ++v) dst[v] = src[v];
        }
    }
}

extern "C" void kernel_launch(void* const* d_in, const int* in_sizes, int n_in,
                              void* d_out, int out_size) {
    (void)in_sizes; (void)n_in; (void)out_size;
    cudaFuncSetAttribute(stacknet_scan, cudaFuncAttributeMaxDynamicSharedMemorySize, SMEM_BYTES);
    const float* x        = (const float*)d_in[0];
    const float* stack_in = (const float*)d_in[1];
    const int*   ptrs     = (const int*)  d_in[2];
    const float* W1 = (const float*)d_in[3];  const float* b1 = (const float*)d_in[4];
    const float* W2 = (const float*)d_in[5];  const float* b2 = (const float*)d_in[6];
    const float* Ws = (const float*)d_in[7];  const float* bs = (const float*)d_in[8];
    const float* Wp = (const float*)d_in[9];  const float* bp = (const float*)d_in[10];
    const float* Wv = (const float*)d_in[11]; const float* bv = (const float*)d_in[12];
    stacknet_scan<<<B_ / G_, NTHR, SMEM_BYTES>>>(
        x, stack_in, ptrs, W1, b1, W2, b2, Ws, bs, Wp, bp, Wv, bv, (float*)d_out);
}

// round 8
// speedup vs baseline: 1.2826x; 1.2826x over previous
#include <cuda_runtime.h>

#define B_   4096
#define T_   64
#define OBS_ 64
#define H_   64
#define A_   8
#define S_   201
#define G_   32
#define NTHR 256
#define STI  36    // InT/Ht/Pt stride (floats): 32 elems + 4 pad, 16B-aligned
#define STB  68    // pm/pp buffer stride

typedef unsigned long long u64;
typedef unsigned int u32;

__device__ __forceinline__ u64 fma2(u64 a, u64 b, u64 c) {
    u64 d;
    asm("fma.rn.f32x2 %0, %1, %2, %3;" : "=l"(d) : "l"(a), "l"(b), "l"(c));
    return d;
}
__device__ __forceinline__ u64 pack2(float x, float y) {
    u64 d;
    asm("mov.b64 %0, {%1, %2};" : "=l"(d) : "r"(__float_as_uint(x)), "r"(__float_as_uint(y)));
    return d;
}
__device__ __forceinline__ float2 unpack2(u64 a) {
    u32 lo, hi;
    asm("mov.b64 {%0, %1}, %2;" : "=r"(lo), "=r"(hi) : "l"(a));
    float2 r; r.x = __uint_as_float(lo); r.y = __uint_as_float(hi);
    return r;
}

// XLA/Eigen f32 fast-tanh clone — decision-critical, validated R3/R5/R7. DO NOT TOUCH.
__device__ __forceinline__ float tanh_xla(float x) {
    float xc = fminf(fmaxf(x, -7.90531110763549805f), 7.90531110763549805f);
    float x2 = xc * xc;
    float p = -2.76076847742355e-16f;
    p = __fmaf_rn(p, x2, 2.00018790482477e-13f);
    p = __fmaf_rn(p, x2, -8.60467152213735e-11f);
    p = __fmaf_rn(p, x2, 5.12229709037114e-08f);
    p = __fmaf_rn(p, x2, 1.48572235717979e-05f);
    p = __fmaf_rn(p, x2, 6.37261928875436e-04f);
    p = __fmaf_rn(p, x2, 4.89352455891786e-03f);
    float num = xc * p;
    float q = 1.19825839466702e-06f;
    q = __fmaf_rn(q, x2, 1.18534705686654e-04f);
    q = __fmaf_rn(q, x2, 2.26843463243900e-03f);
    q = __fmaf_rn(q, x2, 4.89352518554385e-03f);
    float r = __fdiv_rn(num, q);
    return (fabsf(x) < 0.0004f) ? x : r;
}

#define OFF_VAL ((size_t)B_ * T_ * A_)
#define OFF_STK (OFF_VAL + (size_t)T_ * B_)
#define OFF_PTR (OFF_STK + (size_t)B_ * S_ * H_)

// shared memory layout (float offsets)
#define SM_W1T   0                       // [128][64]
#define SM_W2T   (SM_W1T + 8192)         // [64][64]
#define SM_WST   (SM_W2T + 4096)         // [64][3]
#define SM_WHT   (SM_WST + 192)          // [64][9]
#define SM_B1    (SM_WHT + 576)
#define SM_B2    (SM_B1 + 64)
#define SM_BSS   (SM_B2 + 64)            // 4
#define SM_BHS   (SM_BSS + 4)            // 12 (9 used)
#define SM_IN0   (SM_BHS + 12)           // [128][STI]
#define SM_IN1   (SM_IN0 + 128 * STI)    // [128][STI]
#define SM_HT    (SM_IN1 + 128 * STI)    // [64][STI]
#define SM_PT    (SM_HT + 64 * STI)      // [64][STI]
#define SM_PMB   (SM_PT + 64 * STI)      // [32][STB]
#define SM_PPB   (SM_PMB + 32 * STB)     // [32][STB]
#define SM_LS    (SM_PPB + 32 * STB)     // [32][4]
#define SM_INTS  (SM_LS + 128)           // ptrS(32) + wbits(224)
#define SMEM_FLOATS (SM_INTS + 256)
#define SMEM_BYTES  (SMEM_FLOATS * 4)

__global__ void __launch_bounds__(NTHR, 1) stacknet_scan(
    const float* __restrict__ x,   const float* __restrict__ stack_in,
    const int*   __restrict__ ptr_in,
    const float* __restrict__ W1,  const float* __restrict__ b1,
    const float* __restrict__ W2,  const float* __restrict__ b2,
    const float* __restrict__ Ws,  const float* __restrict__ bsv,
    const float* __restrict__ Wp,  const float* __restrict__ bp,
    const float* __restrict__ Wv,  const float* __restrict__ bv,
    float* __restrict__ out)
{
    extern __shared__ float sm[];
    float* W1t = sm + SM_W1T;
    float* W2t = sm + SM_W2T;
    float* Wst = sm + SM_WST;
    float* Wht = sm + SM_WHT;
    float* b1s = sm + SM_B1;
    float* b2s = sm + SM_B2;
    float* bss = sm + SM_BSS;
    float* bhs = sm + SM_BHS;
    float* Ht  = sm + SM_HT;      // [k][e]
    float* Pt  = sm + SM_PT;      // [j][e]
    float* pmb = sm + SM_PMB;     // [e][f] candidate next-top (pop)
    float* ppb = sm + SM_PPB;     // [e][f] candidate next-top (push)
    float* Ls  = sm + SM_LS;
    int*   ptrS  = (int*)(sm + SM_INTS);
    u32*   wbits = (u32*)(ptrS + 32);   // [32][7]

    const int tid  = threadIdx.x;
    const int base = blockIdx.x * G_;

    // ---- weight prologue (transposed [k][j]) ----
    for (int i = tid; i < 8192; i += NTHR) { int j = i >> 7, k = i & 127; W1t[k * 64 + j] = W1[i]; }
    for (int i = tid; i < 4096; i += NTHR) { int j = i >> 6, k = i & 63;  W2t[k * 64 + j] = W2[i]; }
    for (int i = tid; i < 192;  i += NTHR) { int h = i >> 6, k = i & 63;  Wst[k * 3 + h] = Ws[i]; }
    for (int i = tid; i < 512;  i += NTHR) { int h = i >> 6, k = i & 63;  Wht[k * 9 + h] = Wp[i]; }
    for (int i = tid; i < 64;   i += NTHR) { Wht[i * 9 + 8] = Wv[i]; }
    if (tid < 64) { b1s[tid] = b1[tid]; b2s[tid] = b2[tid]; }
    if (tid < 3)              bss[tid] = bsv[tid];
    if (tid >= 3 && tid < 11) bhs[tid - 3] = bp[tid - 3];
    if (tid == 11)            bhs[8] = bv[0];
    for (int i = tid; i < G_ * 7; i += NTHR) wbits[i] = 0;
    if (tid < G_) ptrS[tid] = ptr_in[base + tid];

    // ---- initial InT (buffer 0): concat(x_0, top0), transposed [f][e] ----
    {
        float* In0 = sm + SM_IN0;
        for (int i = tid; i < G_ * 128; i += NTHR) {
            int e = i & 31, f = i >> 5;
            float v;
            if (f < 64) v = x[(size_t)(base + e) * T_ * OBS_ + f];
            else {
                int p0 = ptr_in[base + e];
                v = stack_in[((size_t)(base + e) * S_ + p0) * H_ + (f - 64)];
            }
            In0[f * STI + e] = v;
        }
    }
    __syncthreads();

    // matmul map (tid<128): rows e = 4*rg..4*rg+3, cols j = 4*cg..4*cg+3
    const int rg = tid & 7, cg = tid >> 3;
    // IO map (tid<128): element e, segment seg (features seg*16..seg*16+15)
    const int e = tid & 31, seg = tid >> 5;

    const size_t srow = (size_t)(base + e) * S_;
    float* ostk = out + OFF_STK;

    float* InCur = sm + SM_IN0;
    float* InNxt = sm + SM_IN1;
    int pcur = 0;

    for (int t = 0; t < T_; ++t) {
        __syncthreads();   // A: InT(t) complete; stage-D writes of t-1 visible

        if (tid < 128) {
            // ---- W1: [32x128]@[128x64], 4x4 tile ----
            u64 a00 = 0, a01 = 0, a10 = 0, a11 = 0, a20 = 0, a21 = 0, a30 = 0, a31 = 0;
            const float* inb = InCur + 4 * rg;
            const float* wb  = W1t + 4 * cg;
            #pragma unroll 4
            for (int k = 0; k < 128; ++k) {
                float4 fin = *(const float4*)(inb + k * STI);
                ulonglong2 wv = *(const ulonglong2*)(wb + k * 64);
                u64 i0 = pack2(fin.x, fin.x), i1 = pack2(fin.y, fin.y);
                u64 i2 = pack2(fin.z, fin.z), i3 = pack2(fin.w, fin.w);
                a00 = fma2(i0, wv.x, a00); a01 = fma2(i0, wv.y, a01);
                a10 = fma2(i1, wv.x, a10); a11 = fma2(i1, wv.y, a11);
                a20 = fma2(i2, wv.x, a20); a21 = fma2(i2, wv.y, a21);
                a30 = fma2(i3, wv.x, a31 * 0 + a30); a31 = fma2(i3, wv.y, a31);
            }
            float2 r0a = unpack2(a00), r0b = unpack2(a01);
            float2 r1a = unpack2(a10), r1b = unpack2(a11);
            float2 r2a = unpack2(a20), r2b = unpack2(a21);
            float2 r3a = unpack2(a30), r3b = unpack2(a31);
            int j0 = 4 * cg;
            float bj0 = b1s[j0], bj1 = b1s[j0 + 1], bj2 = b1s[j0 + 2], bj3 = b1s[j0 + 3];
            float4 c0 = make_float4(tanh_xla(r0a.x + bj0), tanh_xla(r1a.x + bj0),
                                    tanh_xla(r2a.x + bj0), tanh_xla(r3a.x + bj0));
            float4 c1 = make_float4(tanh_xla(r0a.y + bj1), tanh_xla(r1a.y + bj1),
                                    tanh_xla(r2a.y + bj1), tanh_xla(r3a.y + bj1));
            float4 c2 = make_float4(tanh_xla(r0b.x + bj2), tanh_xla(r1b.x + bj2),
                                    tanh_xla(r2b.x + bj2), tanh_xla(r3b.x + bj2));
            float4 c3 = make_float4(tanh_xla(r0b.y + bj3), tanh_xla(r1b.y + bj3),
                                    tanh_xla(r2b.y + bj3), tanh_xla(r3b.y + bj3));
            *(float4*)&Ht[j0 * STI + 4 * rg]       = c0;
            *(float4*)&Ht[(j0 + 1) * STI + 4 * rg] = c1;
            *(float4*)&Ht[(j0 + 2) * STI + 4 * rg] = c2;
            *(float4*)&Ht[(j0 + 3) * STI + 4 * rg] = c3;
        } else if (tid < 160) {
            // ---- warp 4: policy/value heads for step t-1 (reads Pt(t-1)) ----
            if (t > 0) {
                int ee = tid - 128;
                float acc[9];
                #pragma unroll
                for (int h = 0; h < 9; ++h) acc[h] = 0.0f;
                #pragma unroll 4
                for (int k = 0; k < 64; ++k) {
                    float pv = Pt[k * STI + ee];
                    #pragma unroll
                    for (int h = 0; h < 9; ++h)
                        acc[h] = __fmaf_rn(pv, Wht[k * 9 + h], acc[h]);
                }
                #pragma unroll
                for (int h = 0; h < 8; ++h)
                    out[((size_t)(base + ee) * T_ + (t - 1)) * A_ + h] = acc[h] + bhs[h];
                out[OFF_VAL + (size_t)(t - 1) * B_ + (base + ee)] = acc[8] + bhs[8];
            }
        } else if (tid < 192) {
            // ---- warp 5: stream x_{t+1} into InNxt x-rows ----
            if (t + 1 < T_) {
                int ee = tid - 160;
                const float4* xsrc = (const float4*)(x + (size_t)(base + ee) * T_ * OBS_
                                                       + (size_t)(t + 1) * OBS_);
                #pragma unroll 4
                for (int i = 0; i < 16; ++i) {
                    float4 v = xsrc[i];
                    int f = 4 * i;
                    InNxt[f * STI + ee]       = v.x;
                    InNxt[(f + 1) * STI + ee] = v.y;
                    InNxt[(f + 2) * STI + ee] = v.z;
                    InNxt[(f + 3) * STI + ee] = v.w;
                }
            }
        } else {
            // ---- warps 6,7: prefetch candidate next-top rows (pop / push) ----
            if (t + 1 < T_) {
                int idx = tid - 192;
                int ee = idx & 31, which = idx >> 5;
                int p = ptrS[ee];
                int row = which ? (p + 1) : (p > 0 ? p - 1 : 0);
                const float* sb = ((wbits[ee * 7 + (row >> 5)] >> (row & 31)) & 1u)
                                  ? ostk : stack_in;
                const float4* src = (const float4*)(sb + ((size_t)(base + ee) * S_ + row) * H_);
                float* dst = (which ? ppb : pmb) + ee * STB;
                #pragma unroll 4
                for (int i = 0; i < 16; ++i) *(float4*)(dst + 4 * i) = src[i];
            }
        }
        __syncthreads();   // B: Ht ready

        if (tid < 128) {
            // ---- W2: [32x64]@[64x64], 4x4 tile ----
            u64 a00 = 0, a01 = 0, a10 = 0, a11 = 0, a20 = 0, a21 = 0, a30 = 0, a31 = 0;
            const float* inb = Ht + 4 * rg;
            const float* wb  = W2t + 4 * cg;
            #pragma unroll 4
            for (int k = 0; k < 64; ++k) {
                float4 fin = *(const float4*)(inb + k * STI);
                ulonglong2 wv = *(const ulonglong2*)(wb + k * 64);
                u64 i0 = pack2(fin.x, fin.x), i1 = pack2(fin.y, fin.y);
                u64 i2 = pack2(fin.z, fin.z), i3 = pack2(fin.w, fin.w);
                a00 = fma2(i0, wv.x, a00); a01 = fma2(i0, wv.y, a01);
                a10 = fma2(i1, wv.x, a10); a11 = fma2(i1, wv.y, a11);
                a20 = fma2(i2, wv.x, a20); a21 = fma2(i2, wv.y, a21);
                a30 = fma2(i3, wv.x, a30); a31 = fma2(i3, wv.y, a31);
            }
            float2 r0a = unpack2(a00), r0b = unpack2(a01);
            float2 r1a = unpack2(a10), r1b = unpack2(a11);
            float2 r2a = unpack2(a20), r2b = unpack2(a21);
            float2 r3a = unpack2(a30), r3b = unpack2(a31);
            int j0 = 4 * cg;
            float bj0 = b2s[j0], bj1 = b2s[j0 + 1], bj2 = b2s[j0 + 2], bj3 = b2s[j0 + 3];
            float4 c0 = make_float4(tanh_xla(r0a.x + bj0), tanh_xla(r1a.x + bj0),
                                    tanh_xla(r2a.x + bj0), tanh_xla(r3a.x + bj0));
            float4 c1 = make_float4(tanh_xla(r0a.y + bj1), tanh_xla(r1a.y + bj1),
                                    tanh_xla(r2a.y + bj1), tanh_xla(r3a.y + bj1));
            float4 c2 = make_float4(tanh_xla(r0b.x + bj2), tanh_xla(r1b.x + bj2),
                                    tanh_xla(r2b.x + bj2), tanh_xla(r3b.x + bj2));
            float4 c3 = make_float4(tanh_xla(r0b.y + bj3), tanh_xla(r1b.y + bj3),
                                    tanh_xla(r2b.y + bj3), tanh_xla(r3b.y + bj3));
            *(float4*)&Pt[j0 * STI + 4 * rg]       = c0;
            *(float4*)&Pt[(j0 + 1) * STI + 4 * rg] = c1;
            *(float4*)&Pt[(j0 + 2) * STI + 4 * rg] = c2;
            *(float4*)&Pt[(j0 + 3) * STI + 4 * rg] = c3;
        }
        __syncthreads();   // C: Pt ready

        if (tid < 128) {
            pcur = ptrS[e];                  // race-free: no writer in this stage
        } else if (tid < 224) {
            // ---- stack-head: 96 threads, (e, h) dots; order identical to R3 ----
            int idx = tid - 128;
            int ee = idx / 3, h = idx - 3 * ee;
            float acc = 0.0f;
            #pragma unroll 8
            for (int k = 0; k < 64; ++k)
                acc = __fmaf_rn(Pt[k * STI + ee], Wst[k * 3 + h], acc);
            Ls[ee * 4 + h] = acc + bss[h];
        }
        __syncthreads();   // D: Ls ready

        if (tid < 128) {
            float l0 = Ls[e * 4], l1 = Ls[e * 4 + 1], l2 = Ls[e * 4 + 2];
            int op = 0; float bst = l0;
            if (l1 > bst) { bst = l1; op = 1; }
            if (l2 > bst) { op = 2; }
            if (tid < 32) {     // seg==0 lane per element
                int np = pcur + op - 1; np = np < 0 ? 0 : np;
                ptrS[e] = np;
                if (op == 2) wbits[e * 7 + (pcur >> 5)] |= (1u << (pcur & 31));
            }
            if (op == 2) {
                // push write-through: stack[pcur] = p
                float pv[16];
                #pragma unroll
                for (int i = 0; i < 16; ++i) pv[i] = Pt[(seg * 16 + i) * STI + e];
                float4* dst = (float4*)(ostk + (srow + pcur) * H_ + seg * 16);
                dst[0] = make_float4(pv[0], pv[1], pv[2], pv[3]);
                dst[1] = make_float4(pv[4], pv[5], pv[6], pv[7]);
                dst[2] = make_float4(pv[8], pv[9], pv[10], pv[11]);
                dst[3] = make_float4(pv[12], pv[13], pv[14], pv[15]);
            }
            if (t + 1 < T_) {
                // next top: push -> stack[p+1] (ppb), pop -> stack[p-1] (pmb), noop -> keep
                if (op == 2) {
                    #pragma unroll
                    for (int i = 0; i < 16; ++i) {
                        int f = seg * 16 + i;
                        InNxt[(64 + f) * STI + e] = ppb[e * STB + f];
                    }
                } else if (op == 0) {
                    #pragma unroll
                    for (int i = 0; i < 16; ++i) {
                        int f = seg * 16 + i;
                        InNxt[(64 + f) * STI + e] = pmb[e * STB + f];
                    }
                } else {
                    #pragma unroll
                    for (int i = 0; i < 16; ++i) {
                        int f = seg * 16 + i;
                        InNxt[(64 + f) * STI + e] = InCur[(64 + f) * STI + e];
                    }
                }
            }
        }
        { float* tmp = InCur; InCur = InNxt; InNxt = tmp; }
    }
    __syncthreads();

    // final policy/value for t = T-1 (Pt still holds it)
    if (tid < 32) {
        int ee = tid;
        float acc[9];
        #pragma unroll
        for (int h = 0; h < 9; ++h) acc[h] = 0.0f;
        #pragma unroll 4
        for (int k = 0; k < 64; ++k) {
            float pv = Pt[k * STI + ee];
            #pragma unroll
            for (int h = 0; h < 9; ++h)
                acc[h] = __fmaf_rn(pv, Wht[k * 9 + h], acc[h]);
        }
        #pragma unroll
        for (int h = 0; h < 8; ++h)
            out[((size_t)(base + ee) * T_ + (T_ - 1)) * A_ + h] = acc[h] + bhs[h];
        out[OFF_VAL + (size_t)(T_ - 1) * B_ + (base + ee)] = acc[8] + bhs[8];
        out[OFF_PTR + base + ee] = (float)ptrS[ee];
    }
    __syncthreads();

    // epilogue: copy never-written stack rows from input
    for (int it = tid; it < G_ * S_; it += NTHR) {
        int ee = it / S_, rr = it - S_ * ee;
        if (!((wbits[ee * 7 + (rr >> 5)] >> (rr & 31)) & 1u)) {
            const float4* src = (const float4*)(stack_in + ((size_t)(base + ee) * S_ + rr) * H_);
            float4* dst = (float4*)(out + OFF_STK + ((size_t)(base + ee) * S_ + rr) * H_);
            #pragma unroll
            for (int v = 0; v < 16; ++v) dst[v] = src[v];
        }
    }
}

extern "C" void kernel_launch(void* const* d_in, const int* in_sizes, int n_in,
                              void* d_out, int out_size) {
    (void)in_sizes; (void)n_in; (void)out_size;
    cudaFuncSetAttribute(stacknet_scan, cudaFuncAttributeMaxDynamicSharedMemorySize, SMEM_BYTES);
    const float* x        = (const float*)d_in[0];
    const float* stack_in = (const float*)d_in[1];
    const int*   ptrs     = (const int*)  d_in[2];
    const float* W1 = (const float*)d_in[3];  const float* b1 = (const float*)d_in[4];
    const float* W2 = (const float*)d_in[5];  const float* b2 = (const float*)d_in[6];
    const float* Ws = (const float*)d_in[7];  const float* bs = (const float*)d_in[8];
    const float* Wp = (const float*)d_in[9];  const float* bp = (const float*)d_in[10];
    const float* Wv = (const float*)d_in[11]; const float* bv = (const float*)d_in[12];
    stacknet_scan<<<B_ / G_, NTHR, SMEM_BYTES>>>(
        x, stack_in, ptrs, W1, b1, W2, b2, Ws, bs, Wp, bp, Wv, bv, (float*)d_out);
}